// round 15
// baseline (speedup 1.0000x reference)
#include <cuda_runtime.h>
#include <cuda_fp16.h>
#include <math.h>

#define F8c   16
#define F2c   64
#define DIM6c 455
#define PAD6  480
#define Gc    4096
#define MROWS 8192     // B*T*F8
#define BTc   512      // B*T
#define XROWS 16384    // B*H*C
#define TROWS 32768    // B*T*F2
#define NBPAD 512
#define DSCALE   256.0f
#define DUNSCALE (1.0f/256.0f)

__device__ __forceinline__ unsigned int smem_u32(const void* p) {
    return (unsigned int)__cvta_generic_to_shared(p);
}
#define CP_ASYNC16(dst, src) \
    asm volatile("cp.async.cg.shared.global [%0], [%1], 16;" :: "r"(dst), "l"(src))
#define CP_ASYNC8(dst, src) \
    asm volatile("cp.async.ca.shared.global [%0], [%1], 8;" :: "r"(dst), "l"(src))
#define CP_COMMIT()  asm volatile("cp.async.commit_group;")
#define CP_WAIT1()   asm volatile("cp.async.wait_group 1;")
#define CP_WAIT0()   asm volatile("cp.async.wait_group 0;")

#define MMA_F16(c0,c1,c2,c3,a0,a1,a2,a3,b0,b1) \
    asm volatile("mma.sync.aligned.m16n8k16.row.col.f32.f16.f16.f32 " \
        "{%0,%1,%2,%3}, {%4,%5,%6,%7}, {%8,%9}, {%0,%1,%2,%3};" \
        : "+f"(c0), "+f"(c1), "+f"(c2), "+f"(c3) \
        : "r"(a0), "r"(a1), "r"(a2), "r"(a3), "r"(b0), "r"(b1))

#define LDSM4(r0,r1,r2,r3,addr) \
    asm volatile("ldmatrix.sync.aligned.m8n8.x4.shared.b16 {%0,%1,%2,%3}, [%4];" \
        : "=r"(r0), "=r"(r1), "=r"(r2), "=r"(r3) : "r"(addr))

// -------- scratch --------
__device__ float   g_H  [MROWS * 10];
__device__ __half  g_sigH[(size_t)MROWS * Gc];   // fp16 sig, [m][k]
__device__ __half  g_BnH [(size_t)NBPAD * Gc];   // fp16 Dout^T * 256, [n][k]
__device__ __half  g_Ah [4128768];               // per-l A_l fp16 [(bt*d+m)][Kp=16(d+1)]
__device__ __half  g_Bh [516096];                // per-l B_l fp16 [(g2*d+v)][Kp]
__device__ __half  g_TJh[(size_t)TROWS * PAD6];  // fp16 traj455, padded
__device__ __half  g_xH [(size_t)XROWS * PAD6];  // fp16 x, padded
__device__ __half  g_icoH[64 * PAD6];            // fp16 ico, padded

// per-l bases in halves: size = 8192*d*(d+1) (A), 1024*d*(d+1) (B)
#define AB0h 0
#define AB1h 16384
#define AB2h 114688
#define AB3h 360448
#define AB4h 819200
#define AB5h 1556480
#define AB6h 2637824
#define BB0h 0
#define BB1h 2048
#define BB2h 14336
#define BB3h 45056
#define BB4h 102400
#define BB5h 194560
#define BB6h 329728

// ======================= kPrep bodies =======================
__device__ __forceinline__ void kH_body(const float* __restrict__ traj,
                                        const float* __restrict__ w1s,
                                        const float* __restrict__ w1v,
                                        int b, int tid) {
    int row = b * 256 + tid;
    if (row >= MROWS) return;
    int bt = row >> 4, c = row & 15;
    const float* tr = traj + bt * 10;
    float tv[9];
    #pragma unroll
    for (int q = 0; q < 9; q++) tv[q] = tr[q];
    float s = tr[9];
    float* out = g_H + row * 10;
    out[0] = s * w1s[c];
    const float inv3 = 0.57735026918962576f;
    #pragma unroll
    for (int v = 0; v < 3; v++) {
        #pragma unroll
        for (int m = 0; m < 3; m++) {
            float a = 0.f;
            #pragma unroll
            for (int u = 0; u < 3; u++)
                a += tv[u*3 + m] * w1v[c*9 + u*3 + v];
            out[1 + v*3 + m] = a * inv3;
        }
    }
}

__device__ __forceinline__ void kCvtT_body(const float* __restrict__ Dout,
                                           unsigned short (*t)[33], int b, int tidx) {
    const int k0 = (b & 127) * 32;
    const int n0 = (b >> 7) * 32;
    const int tx = tidx & 31, ty = tidx >> 5;
    #pragma unroll
    for (int j = 0; j < 4; j++) {
        int k = k0 + ty + j*8, n = n0 + tx;
        float v = (n < DIM6c) ? Dout[(size_t)k * DIM6c + n] * DSCALE : 0.f;
        t[ty + j*8][tx] = __half_as_ushort(__float2half_rn(v));
    }
    __syncthreads();
    #pragma unroll
    for (int j = 0; j < 4; j++) {
        int n = n0 + ty + j*8, k = k0 + tx;
        g_BnH[(size_t)n * Gc + k] = __ushort_as_half(t[tx][ty + j*8]);
    }
}

template<int L, int BBASE>
__device__ __forceinline__ void kWt_body(const float* __restrict__ wl, int lb, int tid) {
    constexpr int d  = 2*L + 1;
    constexpr int Kp = 16 * (d + 1);
    int idx = lb * 256 + tid;
    if (idx >= 64 * d * Kp) return;
    int n = idx / Kp, k = idx - n * Kp;
    int g2 = n / d, v = n - g2 * d;
    __half val = __float2half_rn(0.f);
    if (k < 16 * d) {
        int f = k / d, u = k - f * d;
        val = __float2half_rn(wl[((f*64 + g2) * d + u) * d + v]);
    }
    g_Bh[BBASE + idx] = val;
}

// zero the k-pad region of g_Ah (16 halves per row)
__device__ __forceinline__ void kZA_body(int b, int tid) {
    int g = b * 256 + tid;
    int e, Kp, ab, d;
    if      (g <   8192) { d=1;  ab=AB0h; e=g;          }
    else if (g <  32768) { d=3;  ab=AB1h; e=g -   8192; }
    else if (g <  73728) { d=5;  ab=AB2h; e=g -  32768; }
    else if (g < 131072) { d=7;  ab=AB3h; e=g -  73728; }
    else if (g < 204800) { d=9;  ab=AB4h; e=g - 131072; }
    else if (g < 294912) { d=11; ab=AB5h; e=g - 204800; }
    else if (g < 401408) { d=13; ab=AB6h; e=g - 294912; }
    else return;
    Kp = 16 * (d + 1);
    int row = e >> 4, kk = e & 15;
    g_Ah[ab + row * Kp + 16*d + kk] = __float2half_rn(0.f);
}

__device__ __forceinline__ void kXC_body(const float* __restrict__ x, int b, int tid) {
    int idx2 = b * 256 + tid;
    int r = idx2 / 240, j2 = idx2 - r * 240;
    int j = j2 * 2;
    float v0 = (j     < DIM6c) ? x[(size_t)r * DIM6c + j    ] : 0.f;
    float v1 = (j + 1 < DIM6c) ? x[(size_t)r * DIM6c + j + 1] : 0.f;
    *(__half2*)(g_xH + (size_t)r * PAD6 + j) = __floats2half2_rn(v0, v1);
}

__device__ __forceinline__ void kAux_body(const float* __restrict__ ico, int I,
                                          int b, int tid) {
    int idx = b * 256 + tid;
    if (idx < 64 * PAD6) {
        int n = idx / PAD6, j = idx - n * PAD6;
        g_icoH[idx] = (n < I && j < DIM6c) ?
            __float2half_rn(ico[(size_t)n * DIM6c + j]) : __float2half_rn(0.f);
    } else {
        int k = idx - 64 * PAD6;
        if (k < TROWS * 25) {
            int r = k / 25, j = DIM6c + (k - r * 25);
            g_TJh[(size_t)r * PAD6 + j] = __float2half_rn(0.f);
        }
    }
}

// block ranges
#define NB_H   32
#define NB_CVT 2048
#define NB_WT  2016
#define NB_ZA  1568
#define NB_XC  15360
#define NB_AUX 3320
#define O_CVT  (NB_H)
#define O_WT   (O_CVT + NB_CVT)
#define O_ZA   (O_WT + NB_WT)
#define O_XC   (O_ZA + NB_ZA)
#define O_AUX  (O_XC + NB_XC)
#define NB_ALL (O_AUX + NB_AUX)

__global__ __launch_bounds__(256) void kPrep(
    const float* traj, const float* w1s, const float* w1v,
    const float* Dout, const float* x, const float* ico, int I,
    const float* w0, const float* w1, const float* w2p, const float* w3,
    const float* w4, const float* w5, const float* w6) {
    __shared__ unsigned short t[32][33];
    const int b = blockIdx.x, tid = threadIdx.x;
    if (b < NB_H) {
        kH_body(traj, w1s, w1v, b, tid);
    } else if (b < O_WT) {
        kCvtT_body(Dout, t, b - O_CVT, tid);
    } else if (b < O_ZA) {
        int lb = b - O_WT;
        if      (lb < 8)    kWt_body<0,BB0h>(w0,  lb,        tid);
        else if (lb < 56)   kWt_body<1,BB1h>(w1,  lb - 8,    tid);
        else if (lb < 176)  kWt_body<2,BB2h>(w2p, lb - 56,   tid);
        else if (lb < 400)  kWt_body<3,BB3h>(w3,  lb - 176,  tid);
        else if (lb < 760)  kWt_body<4,BB4h>(w4,  lb - 400,  tid);
        else if (lb < 1288) kWt_body<5,BB5h>(w5,  lb - 760,  tid);
        else                kWt_body<6,BB6h>(w6,  lb - 1288, tid);
    } else if (b < O_XC) {
        kZA_body(b - O_ZA, tid);
    } else if (b < O_AUX) {
        kXC_body(x, b - O_XC, tid);
    } else {
        kAux_body(ico, I, b - O_AUX, tid);
    }
}

// ============ kSig: g_sigH[m][k] = fp16(relu(H[m].Din[k])), half2 stores ====
__global__ __launch_bounds__(256) void kSig(const float* __restrict__ Din) {
    __shared__ float Hs[32][10];
    const int m0 = blockIdx.y * 32;
    const int k0 = blockIdx.x * 512 + threadIdx.x * 2;
    for (int i = threadIdx.x; i < 320; i += 256)
        Hs[i/10][i%10] = g_H[m0*10 + i];
    __syncthreads();
    float dr0[10], dr1[10];
    #pragma unroll
    for (int q = 0; q < 10; q++) { dr0[q] = Din[k0*10 + q]; dr1[q] = Din[k0*10 + 10 + q]; }
    #pragma unroll 4
    for (int m = 0; m < 32; m++) {
        float a0 = 0.f, a1 = 0.f;
        #pragma unroll
        for (int q = 0; q < 10; q++) { a0 += Hs[m][q] * dr0[q]; a1 += Hs[m][q] * dr1[q]; }
        __half2 h = __floats2half2_rn(fmaxf(a0, 0.f), fmaxf(a1, 0.f));
        *(__half2*)(g_sigH + (size_t)(m0 + m) * Gc + k0) = h;
    }
}

// ===== scatter one C element into per-l fp16 A ([btm][fu], padded Kp) =====
__device__ __forceinline__ void scatterA(int row, int col, float val) {
    if (col >= DIM6c) return;
    __half tv = __float2half_rn(val);
    int bt = row >> 4, f = row & 15;
    if (col < 1) {
        g_Ah[AB0h + bt * 32 + f] = tv;
    } else if (col < 10) {
        int r = col - 1, u = r / 3, m = r - u*3;
        g_Ah[AB1h + (bt*3 + m) * 64 + f*3 + u] = tv;
    } else if (col < 35) {
        int r = col - 10, u = r / 5, m = r - u*5;
        g_Ah[AB2h + (bt*5 + m) * 96 + f*5 + u] = tv;
    } else if (col < 84) {
        int r = col - 35, u = r / 7, m = r - u*7;
        g_Ah[AB3h + (bt*7 + m) * 128 + f*7 + u] = tv;
    } else if (col < 165) {
        int r = col - 84, u = r / 9, m = r - u*9;
        g_Ah[AB4h + (bt*9 + m) * 160 + f*9 + u] = tv;
    } else if (col < 286) {
        int r = col - 165, u = r / 11, m = r - u*11;
        g_Ah[AB5h + (bt*11 + m) * 192 + f*11 + u] = tv;
    } else {
        int r = col - 286, u = r / 13, m = r - u*13;
        g_Ah[AB6h + (bt*13 + m) * 224 + f*13 + u] = tv;
    }
}

// ============ kBh: fp16 mma GEMM with ldmatrix. CTA 128x128, BK=64 ====
#define STAGE_B 18432              // 128*72*2 bytes
__global__ __launch_bounds__(256) void kBh() {
    extern __shared__ __align__(16) char smb[];
    const int n0 = blockIdx.x * 128;
    const int m0 = blockIdx.y * 128;
    const int tid = threadIdx.x;
    const int wid = tid >> 5, lane = tid & 31;
    const int wm = wid >> 1, wn = wid & 1;
    const int lr = lane >> 2;
    const int lc = lane & 3;

    float acc[2][8][4];
    #pragma unroll
    for (int mi = 0; mi < 2; mi++)
        #pragma unroll
        for (int nj = 0; nj < 8; nj++)
            #pragma unroll
            for (int r = 0; r < 4; r++) acc[mi][nj][r] = 0.f;

    auto issue = [&](int buf, int k0) {
        #pragma unroll
        for (int i = 0; i < 4; i++) {
            int id = tid + i*256;
            int row = id >> 3, cc = id & 7;
            CP_ASYNC16(smem_u32(smb + buf*STAGE_B + row*144 + cc*16),
                       g_sigH + (size_t)(m0 + row) * Gc + k0 + cc*8);
            CP_ASYNC16(smem_u32(smb + 2*STAGE_B + buf*STAGE_B + row*144 + cc*16),
                       g_BnH + (size_t)(n0 + row) * Gc + k0 + cc*8);
        }
    };

    issue(0, 0);  CP_COMMIT();
    issue(1, 64); CP_COMMIT();

    const int a_row_in = (lane & 15);
    const int a_koff   = (lane >> 4) << 4;
    const int b_row_in = ((lane >> 4) << 3) + (lane & 7);
    const int b_koff   = ((lane >> 3) & 1) << 4;

    const int NIT = Gc / 64;
    for (int it = 0; it < NIT; it++) {
        const int buf = it & 1;
        const unsigned int Abase = smem_u32(smb + buf*STAGE_B);
        const unsigned int Bbase = smem_u32(smb + 2*STAGE_B + buf*STAGE_B);
        CP_WAIT1();
        __syncthreads();

        #pragma unroll
        for (int kc = 0; kc < 4; kc++) {
            unsigned int afr[2][4];
            #pragma unroll
            for (int mi = 0; mi < 2; mi++) {
                int row = wm*32 + mi*16 + a_row_in;
                LDSM4(afr[mi][0], afr[mi][1], afr[mi][2], afr[mi][3],
                      Abase + row*144 + kc*32 + a_koff);
            }
            unsigned int bfr[8][2];
            #pragma unroll
            for (int njp = 0; njp < 4; njp++) {
                int row = wn*64 + njp*16 + b_row_in;
                LDSM4(bfr[2*njp][0], bfr[2*njp][1], bfr[2*njp+1][0], bfr[2*njp+1][1],
                      Bbase + row*144 + kc*32 + b_koff);
            }
            #pragma unroll
            for (int nj = 0; nj < 8; nj++)
                #pragma unroll
                for (int mi = 0; mi < 2; mi++)
                    MMA_F16(acc[mi][nj][0], acc[mi][nj][1], acc[mi][nj][2], acc[mi][nj][3],
                            afr[mi][0], afr[mi][1], afr[mi][2], afr[mi][3],
                            bfr[nj][0], bfr[nj][1]);
        }
        __syncthreads();
        int nk = (it + 2) * 64;
        if (nk < Gc) issue(buf, nk);
        CP_COMMIT();
    }

    #pragma unroll
    for (int mi = 0; mi < 2; mi++) {
        #pragma unroll
        for (int nj = 0; nj < 8; nj++) {
            int row = m0 + wm*32 + mi*16 + lr;
            int col = n0 + wn*64 + nj*8 + lc*2;
            scatterA(row,     col,     acc[mi][nj][0] * DUNSCALE);
            scatterA(row,     col + 1, acc[mi][nj][1] * DUNSCALE);
            scatterA(row + 8, col,     acc[mi][nj][2] * DUNSCALE);
            scatterA(row + 8, col + 1, acc[mi][nj][3] * DUNSCALE);
        }
    }
}

// ============ kCgemm: per-l C = A_l @ B_l^T (fp16 mma k16), 2-stage, 8B fills
template<int L, int OFF, int ABASE, int BBASE>
__device__ __forceinline__ void kCh_body(__half (*As)[128][36], __half (*Bs)[64][36]) {
    constexpr int d    = 2*L + 1;
    constexpr int Kp   = 16 * (d + 1);
    constexpr int Mdim = 512 * d;
    constexpr int TM   = Mdim / 128;     // 4d
    constexpr int TN   = d;
    const int tile = blockIdx.x;
    if (tile >= TM * TN) return;
    const int m0 = (tile % TM) * 128;
    const int n0 = (tile / TM) * 64;
    const int tid = threadIdx.x;
    const int wid = tid >> 5, lane = tid & 31;
    const int wm = wid >> 1, wn = wid & 1;
    const int lr = lane >> 2, lc = lane & 3;

    float acc[2][4][4];
    #pragma unroll
    for (int mi = 0; mi < 2; mi++)
        #pragma unroll
        for (int nj = 0; nj < 4; nj++)
            #pragma unroll
            for (int r = 0; r < 4; r++) acc[mi][nj][r] = 0.f;

    // 8-byte cp.async: smem row stride is 72B (not 16B-aligned per row)
    auto issue = [&](int buf, int k0) {
        #pragma unroll
        for (int i = 0; i < 4; i++) {
            int id = tid + i*256;              // 1024 chunks: 128 rows x 8
            int row = id >> 3, ch = id & 7;
            CP_ASYNC8(smem_u32((char*)&As[buf][0][0] + row*72 + ch*8),
                      g_Ah + ABASE + (size_t)(m0 + row) * Kp + k0 + ch*4);
        }
        #pragma unroll
        for (int i = 0; i < 2; i++) {
            int id = tid + i*256;              // 512 chunks: 64 rows x 8
            int row = id >> 3, ch = id & 7;
            CP_ASYNC8(smem_u32((char*)&Bs[buf][0][0] + row*72 + ch*8),
                      g_Bh + BBASE + (size_t)(n0 + row) * Kp + k0 + ch*4);
        }
    };

    constexpr int NK = Kp / 32;              // (d+1)/2
    issue(0, 0); CP_COMMIT();
    if (NK > 1) issue(1, 32);
    CP_COMMIT();

    for (int it = 0; it < NK; it++) {
        const int buf = it & 1;
        const unsigned int* A32 = (const unsigned int*)&As[buf][0][0];
        const unsigned int* B32 = (const unsigned int*)&Bs[buf][0][0];
        CP_WAIT1();
        __syncthreads();

        #pragma unroll
        for (int kc = 0; kc < 2; kc++) {
            const int w0 = kc*8 + lc;
            unsigned int afr[2][4];
            #pragma unroll
            for (int mi = 0; mi < 2; mi++) {
                int rb = wm*32 + mi*16 + lr;
                afr[mi][0] = A32[(rb    )*18 + w0    ];
                afr[mi][1] = A32[(rb + 8)*18 + w0    ];
                afr[mi][2] = A32[(rb    )*18 + w0 + 4];
                afr[mi][3] = A32[(rb + 8)*18 + w0 + 4];
            }
            #pragma unroll
            for (int nj = 0; nj < 4; nj++) {
                int nb = wn*32 + nj*8 + lr;
                unsigned int b0 = B32[nb*18 + w0    ];
                unsigned int b1 = B32[nb*18 + w0 + 4];
                #pragma unroll
                for (int mi = 0; mi < 2; mi++)
                    MMA_F16(acc[mi][nj][0], acc[mi][nj][1], acc[mi][nj][2], acc[mi][nj][3],
                            afr[mi][0], afr[mi][1], afr[mi][2], afr[mi][3], b0, b1);
            }
        }
        __syncthreads();
        int nk = (it + 2) * 32;
        if (nk < Kp) issue(buf, nk);
        CP_COMMIT();
    }

    const float scale = 0.25f * rsqrtf((float)d);
    #pragma unroll
    for (int mi = 0; mi < 2; mi++) {
        #pragma unroll
        for (int nj = 0; nj < 4; nj++) {
            #pragma unroll
            for (int rr = 0; rr < 2; rr++) {
                int row = m0 + wm*32 + mi*16 + lr + rr*8;
                int bt = row / d, mm = row - bt * d;
                #pragma unroll
                for (int cc = 0; cc < 2; cc++) {
                    int col = n0 + wn*32 + nj*8 + lc*2 + cc;
                    int g2 = col / d, v = col - g2 * d;
                    g_TJh[(size_t)(bt*64 + g2) * PAD6 + OFF + v*d + mm] =
                        __float2half_rn(acc[mi][nj][rr*2 + cc] * scale);
                }
            }
        }
    }
}
__global__ __launch_bounds__(256) void kCgemm() {
    __shared__ __align__(16) __half As[2][128][36];
    __shared__ __align__(16) __half Bs[2][64][36];
    switch (blockIdx.y) {
        case 0: kCh_body<0,0,  AB0h,BB0h>(As,Bs); break;
        case 1: kCh_body<1,1,  AB1h,BB1h>(As,Bs); break;
        case 2: kCh_body<2,10, AB2h,BB2h>(As,Bs); break;
        case 3: kCh_body<3,35, AB3h,BB3h>(As,Bs); break;
        case 4: kCh_body<4,84, AB4h,BB4h>(As,Bs); break;
        case 5: kCh_body<5,165,AB5h,BB5h>(As,Bs); break;
        case 6: kCh_body<6,286,AB6h,BB6h>(As,Bs); break;
    }
}

// ============ kDmma: fp16 mma, cp.async fills from fp16 padded sources ======
__global__ __launch_bounds__(256) void kDmma(float* __restrict__ out, int I) {
    __shared__ __align__(16) __half As[128][36];
    __shared__ __align__(16) __half Bs[64][36];
    const int r0 = blockIdx.x * 128;
    const __half* Ap = (r0 < XROWS) ? (g_xH + (size_t)r0 * PAD6)
                                    : (g_TJh + (size_t)(r0 - XROWS) * PAD6);
    const int tid = threadIdx.x;
    const int wid = tid >> 5, lane = tid & 31;
    const int wm = wid >> 1, wn = wid & 1;
    const int lr = lane >> 2;
    const int lc = lane & 3;
    const unsigned int* A32 = (const unsigned int*)&As[0][0];
    const unsigned int* B32 = (const unsigned int*)&Bs[0][0];

    float acc[2][4][4];
    #pragma unroll
    for (int mi = 0; mi < 2; mi++)
        #pragma unroll
        for (int nj = 0; nj < 4; nj++)
            #pragma unroll
            for (int r = 0; r < 4; r++) acc[mi][nj][r] = 0.f;

    for (int j0 = 0; j0 < PAD6; j0 += 32) {
        #pragma unroll
        for (int i = 0; i < 4; i++) {
            int id = tid + i*256;
            int r = id >> 3, ch = id & 7;
            CP_ASYNC8(smem_u32((char*)&As[0][0] + r*72 + ch*8),
                      Ap + (size_t)r * PAD6 + j0 + ch*4);
        }
        #pragma unroll
        for (int i = 0; i < 2; i++) {
            int id = tid + i*256;
            int n = id >> 3, ch = id & 7;
            CP_ASYNC8(smem_u32((char*)&Bs[0][0] + n*72 + ch*8),
                      g_icoH + (size_t)n * PAD6 + j0 + ch*4);
        }
        CP_COMMIT();
        CP_WAIT0();
        __syncthreads();

        #pragma unroll
        for (int kc = 0; kc < 2; kc++) {
            const int w0 = kc*8 + lc;
            unsigned int afr[2][4];
            #pragma unroll
            for (int mi = 0; mi < 2; mi++) {
                int rb = wm*32 + mi*16 + lr;
                afr[mi][0] = A32[(rb    )*18 + w0    ];
                afr[mi][1] = A32[(rb + 8)*18 + w0    ];
                afr[mi][2] = A32[(rb    )*18 + w0 + 4];
                afr[mi][3] = A32[(rb + 8)*18 + w0 + 4];
            }
            #pragma unroll
            for (int nj = 0; nj < 4; nj++) {
                int nb = wn*32 + nj*8 + lr;
                unsigned int b0 = B32[nb*18 + w0    ];
                unsigned int b1 = B32[nb*18 + w0 + 4];
                #pragma unroll
                for (int mi = 0; mi < 2; mi++)
                    MMA_F16(acc[mi][nj][0], acc[mi][nj][1], acc[mi][nj][2], acc[mi][nj][3],
                            afr[mi][0], afr[mi][1], afr[mi][2], afr[mi][3], b0, b1);
            }
        }
        __syncthreads();
    }

    #pragma unroll
    for (int mi = 0; mi < 2; mi++) {
        #pragma unroll
        for (int nj = 0; nj < 4; nj++) {
            int row = r0 + wm*32 + mi*16 + lr;
            int col = wn*32 + nj*8 + lc*2;
            if (col < I) {
                out[(size_t)row * I + col] = acc[mi][nj][0];
                out[(size_t)(row + 8) * I + col] = acc[mi][nj][2];
                if (col + 1 < I) {
                    out[(size_t)row * I + col + 1] = acc[mi][nj][1];
                    out[(size_t)(row + 8) * I + col + 1] = acc[mi][nj][3];
                }
            }
        }
    }
}

extern "C" void kernel_launch(void* const* d_in, const int* in_sizes, int n_in,
                              void* d_out, int out_size) {
    const float *x = nullptr, *traj = nullptr, *w1s = nullptr, *w1v = nullptr;
    const float *Din = nullptr, *Dout = nullptr, *ico = nullptr;
    const float* w2[7] = {};
    int icoN = 60;

    for (int i = 0; i < n_in; i++) {
        int sz = in_sizes[i];
        const float* p = (const float*)d_in[i];
        switch (sz) {
            case 7454720: x    = p; break;
            case 5120:    traj = p; break;
            case 16:      w1s  = p; break;
            case 144:     w1v  = p; break;
            case 40960:   Din  = p; break;
            case 1863680: Dout = p; break;
            case 1024:    w2[0] = p; break;
            case 9216:    w2[1] = p; break;
            case 25600:   w2[2] = p; break;
            case 50176:   w2[3] = p; break;
            case 82944:   w2[4] = p; break;
            case 123904:  w2[5] = p; break;
            case 173056:  w2[6] = p; break;
            default:      ico = p; icoN = sz / DIM6c; break;
        }
    }
    float* out = (float*)d_out;

    const int SMEMB = 4 * STAGE_B;   // 73728 bytes
    cudaFuncSetAttribute(kBh, cudaFuncAttributeMaxDynamicSharedMemorySize, SMEMB);

    kPrep<<<NB_ALL, 256>>>(traj, w1s, w1v, Dout, x, ico, icoN,
                           w2[0], w2[1], w2[2], w2[3], w2[4], w2[5], w2[6]);
    kSig<<<dim3(Gc/512, MROWS/32), 256>>>(Din);

    kBh<<<dim3(4, MROWS/128), 256, SMEMB>>>();

    kCgemm<<<dim3(676, 7), 256>>>();

    kDmma<<<(XROWS + TROWS)/128, 256>>>(out, icoN);
}

// round 16
// speedup vs baseline: 1.0346x; 1.0346x over previous
#include <cuda_runtime.h>
#include <cuda_fp16.h>
#include <math.h>

#define F8c   16
#define F2c   64
#define DIM6c 455
#define PAD6  480
#define Gc    4096
#define MROWS 8192     // B*T*F8
#define BTc   512      // B*T
#define XROWS 16384    // B*H*C
#define TROWS 32768    // B*T*F2
#define NBPAD 512
#define DSCALE   256.0f
#define DUNSCALE (1.0f/256.0f)

__device__ __forceinline__ unsigned int smem_u32(const void* p) {
    return (unsigned int)__cvta_generic_to_shared(p);
}
#define CP_ASYNC16(dst, src) \
    asm volatile("cp.async.cg.shared.global [%0], [%1], 16;" :: "r"(dst), "l"(src))
#define CP_ASYNC8(dst, src) \
    asm volatile("cp.async.ca.shared.global [%0], [%1], 8;" :: "r"(dst), "l"(src))
#define CP_COMMIT()  asm volatile("cp.async.commit_group;")
#define CP_WAIT1()   asm volatile("cp.async.wait_group 1;")
#define CP_WAIT0()   asm volatile("cp.async.wait_group 0;")

#define MMA_F16(c0,c1,c2,c3,a0,a1,a2,a3,b0,b1) \
    asm volatile("mma.sync.aligned.m16n8k16.row.col.f32.f16.f16.f32 " \
        "{%0,%1,%2,%3}, {%4,%5,%6,%7}, {%8,%9}, {%0,%1,%2,%3};" \
        : "+f"(c0), "+f"(c1), "+f"(c2), "+f"(c3) \
        : "r"(a0), "r"(a1), "r"(a2), "r"(a3), "r"(b0), "r"(b1))

#define LDSM4(r0,r1,r2,r3,addr) \
    asm volatile("ldmatrix.sync.aligned.m8n8.x4.shared.b16 {%0,%1,%2,%3}, [%4];" \
        : "=r"(r0), "=r"(r1), "=r"(r2), "=r"(r3) : "r"(addr))

// -------- scratch --------
__device__ float   g_H  [MROWS * 10];
__device__ __half  g_sigH[(size_t)MROWS * Gc];   // fp16 sig, [m][k]
__device__ __half  g_BnH [(size_t)NBPAD * Gc];   // fp16 Dout^T * 256, [n][k]
__device__ __half  g_Ah [4128768];               // per-l A_l fp16 [(bt*d+m)][Kp=16(d+1)]
__device__ __half  g_Bh [516096];                // per-l B_l fp16 [(g2*d+v)][Kp]
__device__ __half  g_TJh[(size_t)TROWS * PAD6];  // fp16 traj455, padded
__device__ __half  g_xH [(size_t)XROWS * PAD6];  // fp16 x, padded
__device__ __half  g_icoH[64 * PAD6];            // fp16 ico, padded

#define AB0h 0
#define AB1h 16384
#define AB2h 114688
#define AB3h 360448
#define AB4h 819200
#define AB5h 1556480
#define AB6h 2637824
#define BB0h 0
#define BB1h 2048
#define BB2h 14336
#define BB3h 45056
#define BB4h 102400
#define BB5h 194560
#define BB6h 329728

// ======================= kPrep bodies =======================
__device__ __forceinline__ void kH_body(const float* __restrict__ traj,
                                        const float* __restrict__ w1s,
                                        const float* __restrict__ w1v,
                                        int b, int tid) {
    int row = b * 256 + tid;
    if (row >= MROWS) return;
    int bt = row >> 4, c = row & 15;
    const float* tr = traj + bt * 10;
    float tv[9];
    #pragma unroll
    for (int q = 0; q < 9; q++) tv[q] = tr[q];
    float s = tr[9];
    float* out = g_H + row * 10;
    out[0] = s * w1s[c];
    const float inv3 = 0.57735026918962576f;
    #pragma unroll
    for (int v = 0; v < 3; v++) {
        #pragma unroll
        for (int m = 0; m < 3; m++) {
            float a = 0.f;
            #pragma unroll
            for (int u = 0; u < 3; u++)
                a += tv[u*3 + m] * w1v[c*9 + u*3 + v];
            out[1 + v*3 + m] = a * inv3;
        }
    }
}

__device__ __forceinline__ void kCvtT_body(const float* __restrict__ Dout,
                                           unsigned short (*t)[33], int b, int tidx) {
    const int k0 = (b & 127) * 32;
    const int n0 = (b >> 7) * 32;
    const int tx = tidx & 31, ty = tidx >> 5;
    #pragma unroll
    for (int j = 0; j < 4; j++) {
        int k = k0 + ty + j*8, n = n0 + tx;
        float v = (n < DIM6c) ? Dout[(size_t)k * DIM6c + n] * DSCALE : 0.f;
        t[ty + j*8][tx] = __half_as_ushort(__float2half_rn(v));
    }
    __syncthreads();
    #pragma unroll
    for (int j = 0; j < 4; j++) {
        int n = n0 + ty + j*8, k = k0 + tx;
        g_BnH[(size_t)n * Gc + k] = __ushort_as_half(t[tx][ty + j*8]);
    }
}

template<int L, int BBASE>
__device__ __forceinline__ void kWt_body(const float* __restrict__ wl, int lb, int tid) {
    constexpr int d  = 2*L + 1;
    constexpr int Kp = 16 * (d + 1);
    int idx = lb * 256 + tid;
    if (idx >= 64 * d * Kp) return;
    int n = idx / Kp, k = idx - n * Kp;
    int g2 = n / d, v = n - g2 * d;
    __half val = __float2half_rn(0.f);
    if (k < 16 * d) {
        int f = k / d, u = k - f * d;
        val = __float2half_rn(wl[((f*64 + g2) * d + u) * d + v]);
    }
    g_Bh[BBASE + idx] = val;
}

__device__ __forceinline__ void kZA_body(int b, int tid) {
    int g = b * 256 + tid;
    int e, Kp, ab, d;
    if      (g <   8192) { d=1;  ab=AB0h; e=g;          }
    else if (g <  32768) { d=3;  ab=AB1h; e=g -   8192; }
    else if (g <  73728) { d=5;  ab=AB2h; e=g -  32768; }
    else if (g < 131072) { d=7;  ab=AB3h; e=g -  73728; }
    else if (g < 204800) { d=9;  ab=AB4h; e=g - 131072; }
    else if (g < 294912) { d=11; ab=AB5h; e=g - 204800; }
    else if (g < 401408) { d=13; ab=AB6h; e=g - 294912; }
    else return;
    Kp = 16 * (d + 1);
    int row = e >> 4, kk = e & 15;
    g_Ah[ab + row * Kp + 16*d + kk] = __float2half_rn(0.f);
}

__device__ __forceinline__ void kXC_body(const float* __restrict__ x, int b, int tid) {
    int idx2 = b * 256 + tid;
    int r = idx2 / 240, j2 = idx2 - r * 240;
    int j = j2 * 2;
    float v0 = (j     < DIM6c) ? x[(size_t)r * DIM6c + j    ] : 0.f;
    float v1 = (j + 1 < DIM6c) ? x[(size_t)r * DIM6c + j + 1] : 0.f;
    *(__half2*)(g_xH + (size_t)r * PAD6 + j) = __floats2half2_rn(v0, v1);
}

__device__ __forceinline__ void kAux_body(const float* __restrict__ ico, int I,
                                          int b, int tid) {
    int idx = b * 256 + tid;
    if (idx < 64 * PAD6) {
        int n = idx / PAD6, j = idx - n * PAD6;
        g_icoH[idx] = (n < I && j < DIM6c) ?
            __float2half_rn(ico[(size_t)n * DIM6c + j]) : __float2half_rn(0.f);
    } else {
        int k = idx - 64 * PAD6;
        if (k < TROWS * 25) {
            int r = k / 25, j = DIM6c + (k - r * 25);
            g_TJh[(size_t)r * PAD6 + j] = __float2half_rn(0.f);
        }
    }
}

#define NB_H   32
#define NB_CVT 2048
#define NB_WT  2016
#define NB_ZA  1568
#define NB_XC  15360
#define NB_AUX 3320
#define O_CVT  (NB_H)
#define O_WT   (O_CVT + NB_CVT)
#define O_ZA   (O_WT + NB_WT)
#define O_XC   (O_ZA + NB_ZA)
#define O_AUX  (O_XC + NB_XC)
#define NB_ALL (O_AUX + NB_AUX)

__global__ __launch_bounds__(256) void kPrep(
    const float* traj, const float* w1s, const float* w1v,
    const float* Dout, const float* x, const float* ico, int I,
    const float* w0, const float* w1, const float* w2p, const float* w3,
    const float* w4, const float* w5, const float* w6) {
    __shared__ unsigned short t[32][33];
    const int b = blockIdx.x, tid = threadIdx.x;
    if (b < NB_H) {
        kH_body(traj, w1s, w1v, b, tid);
    } else if (b < O_WT) {
        kCvtT_body(Dout, t, b - O_CVT, tid);
    } else if (b < O_ZA) {
        int lb = b - O_WT;
        if      (lb < 8)    kWt_body<0,BB0h>(w0,  lb,        tid);
        else if (lb < 56)   kWt_body<1,BB1h>(w1,  lb - 8,    tid);
        else if (lb < 176)  kWt_body<2,BB2h>(w2p, lb - 56,   tid);
        else if (lb < 400)  kWt_body<3,BB3h>(w3,  lb - 176,  tid);
        else if (lb < 760)  kWt_body<4,BB4h>(w4,  lb - 400,  tid);
        else if (lb < 1288) kWt_body<5,BB5h>(w5,  lb - 760,  tid);
        else                kWt_body<6,BB6h>(w6,  lb - 1288, tid);
    } else if (b < O_XC) {
        kZA_body(b - O_ZA, tid);
    } else if (b < O_AUX) {
        kXC_body(x, b - O_XC, tid);
    } else {
        kAux_body(ico, I, b - O_AUX, tid);
    }
}

// ============ kSig ============
__global__ __launch_bounds__(256) void kSig(const float* __restrict__ Din) {
    __shared__ float Hs[32][10];
    const int m0 = blockIdx.y * 32;
    const int k0 = blockIdx.x * 512 + threadIdx.x * 2;
    for (int i = threadIdx.x; i < 320; i += 256)
        Hs[i/10][i%10] = g_H[m0*10 + i];
    __syncthreads();
    float dr0[10], dr1[10];
    #pragma unroll
    for (int q = 0; q < 10; q++) { dr0[q] = Din[k0*10 + q]; dr1[q] = Din[k0*10 + 10 + q]; }
    #pragma unroll 4
    for (int m = 0; m < 32; m++) {
        float a0 = 0.f, a1 = 0.f;
        #pragma unroll
        for (int q = 0; q < 10; q++) { a0 += Hs[m][q] * dr0[q]; a1 += Hs[m][q] * dr1[q]; }
        __half2 h = __floats2half2_rn(fmaxf(a0, 0.f), fmaxf(a1, 0.f));
        *(__half2*)(g_sigH + (size_t)(m0 + m) * Gc + k0) = h;
    }
}

// ===== scatter into per-l fp16 A ([btm][fu], padded Kp) =====
__device__ __forceinline__ void scatterA(int row, int col, float val) {
    if (col >= DIM6c) return;
    __half tv = __float2half_rn(val);
    int bt = row >> 4, f = row & 15;
    if (col < 1) {
        g_Ah[AB0h + bt * 32 + f] = tv;
    } else if (col < 10) {
        int r = col - 1, u = r / 3, m = r - u*3;
        g_Ah[AB1h + (bt*3 + m) * 64 + f*3 + u] = tv;
    } else if (col < 35) {
        int r = col - 10, u = r / 5, m = r - u*5;
        g_Ah[AB2h + (bt*5 + m) * 96 + f*5 + u] = tv;
    } else if (col < 84) {
        int r = col - 35, u = r / 7, m = r - u*7;
        g_Ah[AB3h + (bt*7 + m) * 128 + f*7 + u] = tv;
    } else if (col < 165) {
        int r = col - 84, u = r / 9, m = r - u*9;
        g_Ah[AB4h + (bt*9 + m) * 160 + f*9 + u] = tv;
    } else if (col < 286) {
        int r = col - 165, u = r / 11, m = r - u*11;
        g_Ah[AB5h + (bt*11 + m) * 192 + f*11 + u] = tv;
    } else {
        int r = col - 286, u = r / 13, m = r - u*13;
        g_Ah[AB6h + (bt*13 + m) * 224 + f*13 + u] = tv;
    }
}

// ============ kBh: fp16 mma GEMM with ldmatrix. CTA 128x128, BK=64 ====
#define STAGE_B 18432
__global__ __launch_bounds__(256) void kBh() {
    extern __shared__ __align__(16) char smb[];
    const int n0 = blockIdx.x * 128;
    const int m0 = blockIdx.y * 128;
    const int tid = threadIdx.x;
    const int wid = tid >> 5, lane = tid & 31;
    const int wm = wid >> 1, wn = wid & 1;
    const int lr = lane >> 2;
    const int lc = lane & 3;

    float acc[2][8][4];
    #pragma unroll
    for (int mi = 0; mi < 2; mi++)
        #pragma unroll
        for (int nj = 0; nj < 8; nj++)
            #pragma unroll
            for (int r = 0; r < 4; r++) acc[mi][nj][r] = 0.f;

    auto issue = [&](int buf, int k0) {
        #pragma unroll
        for (int i = 0; i < 4; i++) {
            int id = tid + i*256;
            int row = id >> 3, cc = id & 7;
            CP_ASYNC16(smem_u32(smb + buf*STAGE_B + row*144 + cc*16),
                       g_sigH + (size_t)(m0 + row) * Gc + k0 + cc*8);
            CP_ASYNC16(smem_u32(smb + 2*STAGE_B + buf*STAGE_B + row*144 + cc*16),
                       g_BnH + (size_t)(n0 + row) * Gc + k0 + cc*8);
        }
    };

    issue(0, 0);  CP_COMMIT();
    issue(1, 64); CP_COMMIT();

    const int a_row_in = (lane & 15);
    const int a_koff   = (lane >> 4) << 4;
    const int b_row_in = ((lane >> 4) << 3) + (lane & 7);
    const int b_koff   = ((lane >> 3) & 1) << 4;

    const int NIT = Gc / 64;
    for (int it = 0; it < NIT; it++) {
        const int buf = it & 1;
        const unsigned int Abase = smem_u32(smb + buf*STAGE_B);
        const unsigned int Bbase = smem_u32(smb + 2*STAGE_B + buf*STAGE_B);
        CP_WAIT1();
        __syncthreads();

        #pragma unroll
        for (int kc = 0; kc < 4; kc++) {
            unsigned int afr[2][4];
            #pragma unroll
            for (int mi = 0; mi < 2; mi++) {
                int row = wm*32 + mi*16 + a_row_in;
                LDSM4(afr[mi][0], afr[mi][1], afr[mi][2], afr[mi][3],
                      Abase + row*144 + kc*32 + a_koff);
            }
            unsigned int bfr[8][2];
            #pragma unroll
            for (int njp = 0; njp < 4; njp++) {
                int row = wn*64 + njp*16 + b_row_in;
                LDSM4(bfr[2*njp][0], bfr[2*njp][1], bfr[2*njp+1][0], bfr[2*njp+1][1],
                      Bbase + row*144 + kc*32 + b_koff);
            }
            #pragma unroll
            for (int nj = 0; nj < 8; nj++)
                #pragma unroll
                for (int mi = 0; mi < 2; mi++)
                    MMA_F16(acc[mi][nj][0], acc[mi][nj][1], acc[mi][nj][2], acc[mi][nj][3],
                            afr[mi][0], afr[mi][1], afr[mi][2], afr[mi][3],
                            bfr[nj][0], bfr[nj][1]);
        }
        __syncthreads();
        int nk = (it + 2) * 64;
        if (nk < Gc) issue(buf, nk);
        CP_COMMIT();
    }

    #pragma unroll
    for (int mi = 0; mi < 2; mi++) {
        #pragma unroll
        for (int nj = 0; nj < 8; nj++) {
            int row = m0 + wm*32 + mi*16 + lr;
            int col = n0 + wn*64 + nj*8 + lc*2;
            scatterA(row,     col,     acc[mi][nj][0] * DUNSCALE);
            scatterA(row,     col + 1, acc[mi][nj][1] * DUNSCALE);
            scatterA(row + 8, col,     acc[mi][nj][2] * DUNSCALE);
            scatterA(row + 8, col + 1, acc[mi][nj][3] * DUNSCALE);
        }
    }
}

// ============ kCgemm v3: full-K-resident fp16, one sync, 8 MMA per k16 ======
// smem: A [128][SH] + B [64][SH], SH = Kp+4 halves. Max (d=13): 87552 B.
#define SMEMC 87552
template<int L, int OFF, int ABASE, int BBASE>
__device__ __forceinline__ void kCh_body(char* sm) {
    constexpr int d    = 2*L + 1;
    constexpr int Kp   = 16 * (d + 1);
    constexpr int SH   = Kp + 4;          // half stride; SW words ≡ 2 or 18 mod 32
    constexpr int SW   = SH / 2;
    constexpr int Mdim = 512 * d;
    constexpr int TM   = Mdim / 128;
    constexpr int TN   = d;
    const int tile = blockIdx.x;
    if (tile >= TM * TN) return;
    const int m0 = (tile % TM) * 128;
    const int n0 = (tile / TM) * 64;
    const int tid = threadIdx.x;
    const int wid = tid >> 5, lane = tid & 31;
    const int wm = wid >> 1, wn = wid & 1;
    const int lr = lane >> 2, lc = lane & 3;

    __half* Ash = (__half*)sm;
    __half* Bsh = Ash + 128 * SH;

    // fill entire K extent once (8-byte cp.async; rows 8B-aligned)
    constexpr int C4 = Kp / 4;            // 8B chunks per row
    for (int c = tid; c < 128 * C4; c += 256) {
        int row = c / C4, ch = c - row * C4;
        CP_ASYNC8(smem_u32(Ash + row*SH + ch*4),
                  g_Ah + ABASE + (size_t)(m0 + row) * Kp + ch*4);
    }
    for (int c = tid; c < 64 * C4; c += 256) {
        int row = c / C4, ch = c - row * C4;
        CP_ASYNC8(smem_u32(Bsh + row*SH + ch*4),
                  g_Bh + BBASE + (size_t)(n0 + row) * Kp + ch*4);
    }
    CP_COMMIT();
    CP_WAIT0();
    __syncthreads();

    const unsigned int* A32 = (const unsigned int*)Ash;
    const unsigned int* B32 = (const unsigned int*)Bsh;

    float acc[2][4][4];
    #pragma unroll
    for (int mi = 0; mi < 2; mi++)
        #pragma unroll
        for (int nj = 0; nj < 4; nj++)
            #pragma unroll
            for (int r = 0; r < 4; r++) acc[mi][nj][r] = 0.f;

    #pragma unroll
    for (int kc = 0; kc < d + 1; kc++) {
        const int w0 = kc*8 + lc;
        unsigned int afr[2][4];
        #pragma unroll
        for (int mi = 0; mi < 2; mi++) {
            int rb = wm*32 + mi*16 + lr;
            afr[mi][0] = A32[(rb    )*SW + w0    ];
            afr[mi][1] = A32[(rb + 8)*SW + w0    ];
            afr[mi][2] = A32[(rb    )*SW + w0 + 4];
            afr[mi][3] = A32[(rb + 8)*SW + w0 + 4];
        }
        #pragma unroll
        for (int nj = 0; nj < 4; nj++) {
            int nb = wn*32 + nj*8 + lr;
            unsigned int b0 = B32[nb*SW + w0    ];
            unsigned int b1 = B32[nb*SW + w0 + 4];
            #pragma unroll
            for (int mi = 0; mi < 2; mi++)
                MMA_F16(acc[mi][nj][0], acc[mi][nj][1], acc[mi][nj][2], acc[mi][nj][3],
                        afr[mi][0], afr[mi][1], afr[mi][2], afr[mi][3], b0, b1);
        }
    }

    const float scale = 0.25f * rsqrtf((float)d);
    #pragma unroll
    for (int mi = 0; mi < 2; mi++) {
        #pragma unroll
        for (int nj = 0; nj < 4; nj++) {
            #pragma unroll
            for (int rr = 0; rr < 2; rr++) {
                int row = m0 + wm*32 + mi*16 + lr + rr*8;
                int bt = row / d, mm = row - bt * d;
                #pragma unroll
                for (int cc = 0; cc < 2; cc++) {
                    int col = n0 + wn*32 + nj*8 + lc*2 + cc;
                    int g2 = col / d, v = col - g2 * d;
                    g_TJh[(size_t)(bt*64 + g2) * PAD6 + OFF + v*d + mm] =
                        __float2half_rn(acc[mi][nj][rr*2 + cc] * scale);
                }
            }
        }
    }
}
__global__ __launch_bounds__(256) void kCgemm() {
    extern __shared__ __align__(16) char smc[];
    switch (blockIdx.y) {
        case 0: kCh_body<0,0,  AB0h,BB0h>(smc); break;
        case 1: kCh_body<1,1,  AB1h,BB1h>(smc); break;
        case 2: kCh_body<2,10, AB2h,BB2h>(smc); break;
        case 3: kCh_body<3,35, AB3h,BB3h>(smc); break;
        case 4: kCh_body<4,84, AB4h,BB4h>(smc); break;
        case 5: kCh_body<5,165,AB5h,BB5h>(smc); break;
        case 6: kCh_body<6,286,AB6h,BB6h>(smc); break;
    }
}

// ============ kDmma ============
__global__ __launch_bounds__(256) void kDmma(float* __restrict__ out, int I) {
    __shared__ __align__(16) __half As[128][36];
    __shared__ __align__(16) __half Bs[64][36];
    const int r0 = blockIdx.x * 128;
    const __half* Ap = (r0 < XROWS) ? (g_xH + (size_t)r0 * PAD6)
                                    : (g_TJh + (size_t)(r0 - XROWS) * PAD6);
    const int tid = threadIdx.x;
    const int wid = tid >> 5, lane = tid & 31;
    const int wm = wid >> 1, wn = wid & 1;
    const int lr = lane >> 2;
    const int lc = lane & 3;
    const unsigned int* A32 = (const unsigned int*)&As[0][0];
    const unsigned int* B32 = (const unsigned int*)&Bs[0][0];

    float acc[2][4][4];
    #pragma unroll
    for (int mi = 0; mi < 2; mi++)
        #pragma unroll
        for (int nj = 0; nj < 4; nj++)
            #pragma unroll
            for (int r = 0; r < 4; r++) acc[mi][nj][r] = 0.f;

    for (int j0 = 0; j0 < PAD6; j0 += 32) {
        #pragma unroll
        for (int i = 0; i < 4; i++) {
            int id = tid + i*256;
            int r = id >> 3, ch = id & 7;
            CP_ASYNC8(smem_u32((char*)&As[0][0] + r*72 + ch*8),
                      Ap + (size_t)r * PAD6 + j0 + ch*4);
        }
        #pragma unroll
        for (int i = 0; i < 2; i++) {
            int id = tid + i*256;
            int n = id >> 3, ch = id & 7;
            CP_ASYNC8(smem_u32((char*)&Bs[0][0] + n*72 + ch*8),
                      g_icoH + (size_t)n * PAD6 + j0 + ch*4);
        }
        CP_COMMIT();
        CP_WAIT0();
        __syncthreads();

        #pragma unroll
        for (int kc = 0; kc < 2; kc++) {
            const int w0 = kc*8 + lc;
            unsigned int afr[2][4];
            #pragma unroll
            for (int mi = 0; mi < 2; mi++) {
                int rb = wm*32 + mi*16 + lr;
                afr[mi][0] = A32[(rb    )*18 + w0    ];
                afr[mi][1] = A32[(rb + 8)*18 + w0    ];
                afr[mi][2] = A32[(rb    )*18 + w0 + 4];
                afr[mi][3] = A32[(rb + 8)*18 + w0 + 4];
            }
            #pragma unroll
            for (int nj = 0; nj < 4; nj++) {
                int nb = wn*32 + nj*8 + lr;
                unsigned int b0 = B32[nb*18 + w0    ];
                unsigned int b1 = B32[nb*18 + w0 + 4];
                #pragma unroll
                for (int mi = 0; mi < 2; mi++)
                    MMA_F16(acc[mi][nj][0], acc[mi][nj][1], acc[mi][nj][2], acc[mi][nj][3],
                            afr[mi][0], afr[mi][1], afr[mi][2], afr[mi][3], b0, b1);
            }
        }
        __syncthreads();
    }

    #pragma unroll
    for (int mi = 0; mi < 2; mi++) {
        #pragma unroll
        for (int nj = 0; nj < 4; nj++) {
            int row = r0 + wm*32 + mi*16 + lr;
            int col = wn*32 + nj*8 + lc*2;
            if (col < I) {
                out[(size_t)row * I + col] = acc[mi][nj][0];
                out[(size_t)(row + 8) * I + col] = acc[mi][nj][2];
                if (col + 1 < I) {
                    out[(size_t)row * I + col + 1] = acc[mi][nj][1];
                    out[(size_t)(row + 8) * I + col + 1] = acc[mi][nj][3];
                }
            }
        }
    }
}

extern "C" void kernel_launch(void* const* d_in, const int* in_sizes, int n_in,
                              void* d_out, int out_size) {
    const float *x = nullptr, *traj = nullptr, *w1s = nullptr, *w1v = nullptr;
    const float *Din = nullptr, *Dout = nullptr, *ico = nullptr;
    const float* w2[7] = {};
    int icoN = 60;

    for (int i = 0; i < n_in; i++) {
        int sz = in_sizes[i];
        const float* p = (const float*)d_in[i];
        switch (sz) {
            case 7454720: x    = p; break;
            case 5120:    traj = p; break;
            case 16:      w1s  = p; break;
            case 144:     w1v  = p; break;
            case 40960:   Din  = p; break;
            case 1863680: Dout = p; break;
            case 1024:    w2[0] = p; break;
            case 9216:    w2[1] = p; break;
            case 25600:   w2[2] = p; break;
            case 50176:   w2[3] = p; break;
            case 82944:   w2[4] = p; break;
            case 123904:  w2[5] = p; break;
            case 173056:  w2[6] = p; break;
            default:      ico = p; icoN = sz / DIM6c; break;
        }
    }
    float* out = (float*)d_out;

    const int SMEMB = 4 * STAGE_B;
    cudaFuncSetAttribute(kBh, cudaFuncAttributeMaxDynamicSharedMemorySize, SMEMB);
    cudaFuncSetAttribute(kCgemm, cudaFuncAttributeMaxDynamicSharedMemorySize, SMEMC);

    kPrep<<<NB_ALL, 256>>>(traj, w1s, w1v, Dout, x, ico, icoN,
                           w2[0], w2[1], w2[2], w2[3], w2[4], w2[5], w2[6]);
    kSig<<<dim3(Gc/512, MROWS/32), 256>>>(Din);

    kBh<<<dim3(4, MROWS/128), 256, SMEMB>>>();

    kCgemm<<<dim3(676, 7), 256, SMEMC>>>();

    kDmma<<<(XROWS + TROWS)/128, 256>>>(out, icoN);
}

// round 17
// speedup vs baseline: 1.0866x; 1.0503x over previous
#include <cuda_runtime.h>
#include <cuda_fp16.h>
#include <math.h>

#define F8c   16
#define F2c   64
#define DIM6c 455
#define PAD6  480
#define Gc    4096
#define MROWS 8192     // B*T*F8
#define BTc   512      // B*T
#define XROWS 16384    // B*H*C
#define TROWS 32768    // B*T*F2
#define NBPAD 512
#define DSCALE   256.0f
#define DUNSCALE (1.0f/256.0f)

__device__ __forceinline__ unsigned int smem_u32(const void* p) {
    return (unsigned int)__cvta_generic_to_shared(p);
}
#define CP_ASYNC16(dst, src) \
    asm volatile("cp.async.cg.shared.global [%0], [%1], 16;" :: "r"(dst), "l"(src))
#define CP_ASYNC8(dst, src) \
    asm volatile("cp.async.ca.shared.global [%0], [%1], 8;" :: "r"(dst), "l"(src))
#define CP_COMMIT()  asm volatile("cp.async.commit_group;")
#define CP_WAIT1()   asm volatile("cp.async.wait_group 1;")
#define CP_WAIT0()   asm volatile("cp.async.wait_group 0;")

#define MMA_F16(c0,c1,c2,c3,a0,a1,a2,a3,b0,b1) \
    asm volatile("mma.sync.aligned.m16n8k16.row.col.f32.f16.f16.f32 " \
        "{%0,%1,%2,%3}, {%4,%5,%6,%7}, {%8,%9}, {%0,%1,%2,%3};" \
        : "+f"(c0), "+f"(c1), "+f"(c2), "+f"(c3) \
        : "r"(a0), "r"(a1), "r"(a2), "r"(a3), "r"(b0), "r"(b1))

#define LDSM4(r0,r1,r2,r3,addr) \
    asm volatile("ldmatrix.sync.aligned.m8n8.x4.shared.b16 {%0,%1,%2,%3}, [%4];" \
        : "=r"(r0), "=r"(r1), "=r"(r2), "=r"(r3) : "r"(addr))

// -------- scratch --------
__device__ float   g_H  [MROWS * 10];
__device__ __half  g_sigH[(size_t)MROWS * Gc];   // fp16 sig, [m][k]
__device__ __half  g_BnH [(size_t)NBPAD * Gc];   // fp16 Dout^T * 256, [n][k]
__device__ __half  g_Ah [4128768];               // per-l A_l fp16 [(bt*d+m)][Kp=16(d+1)]
__device__ __half  g_Bh [516096];                // per-l B_l fp16 [(g2*d+v)][Kp]
__device__ __half  g_TJh[(size_t)TROWS * PAD6];  // fp16 traj455, padded
__device__ __half  g_xH [(size_t)XROWS * PAD6];  // fp16 x, padded
__device__ __half  g_icoH[64 * PAD6];            // fp16 ico, padded

#define AB0h 0
#define AB1h 16384
#define AB2h 114688
#define AB3h 360448
#define AB4h 819200
#define AB5h 1556480
#define AB6h 2637824
#define BB0h 0
#define BB1h 2048
#define BB2h 14336
#define BB3h 45056
#define BB4h 102400
#define BB5h 194560
#define BB6h 329728

// ======================= kPrep bodies =======================
__device__ __forceinline__ void kH_body(const float* __restrict__ traj,
                                        const float* __restrict__ w1s,
                                        const float* __restrict__ w1v,
                                        int b, int tid) {
    int row = b * 256 + tid;
    if (row >= MROWS) return;
    int bt = row >> 4, c = row & 15;
    const float* tr = traj + bt * 10;
    float tv[9];
    #pragma unroll
    for (int q = 0; q < 9; q++) tv[q] = tr[q];
    float s = tr[9];
    float* out = g_H + row * 10;
    out[0] = s * w1s[c];
    const float inv3 = 0.57735026918962576f;
    #pragma unroll
    for (int v = 0; v < 3; v++) {
        #pragma unroll
        for (int m = 0; m < 3; m++) {
            float a = 0.f;
            #pragma unroll
            for (int u = 0; u < 3; u++)
                a += tv[u*3 + m] * w1v[c*9 + u*3 + v];
            out[1 + v*3 + m] = a * inv3;
        }
    }
}

__device__ __forceinline__ void kCvtT_body(const float* __restrict__ Dout,
                                           unsigned short (*t)[33], int b, int tidx) {
    const int k0 = (b & 127) * 32;
    const int n0 = (b >> 7) * 32;
    const int tx = tidx & 31, ty = tidx >> 5;
    #pragma unroll
    for (int j = 0; j < 4; j++) {
        int k = k0 + ty + j*8, n = n0 + tx;
        float v = (n < DIM6c) ? Dout[(size_t)k * DIM6c + n] * DSCALE : 0.f;
        t[ty + j*8][tx] = __half_as_ushort(__float2half_rn(v));
    }
    __syncthreads();
    #pragma unroll
    for (int j = 0; j < 4; j++) {
        int n = n0 + ty + j*8, k = k0 + tx;
        g_BnH[(size_t)n * Gc + k] = __ushort_as_half(t[tx][ty + j*8]);
    }
}

template<int L, int BBASE>
__device__ __forceinline__ void kWt_body(const float* __restrict__ wl, int lb, int tid) {
    constexpr int d  = 2*L + 1;
    constexpr int Kp = 16 * (d + 1);
    int idx = lb * 256 + tid;
    if (idx >= 64 * d * Kp) return;
    int n = idx / Kp, k = idx - n * Kp;
    int g2 = n / d, v = n - g2 * d;
    __half val = __float2half_rn(0.f);
    if (k < 16 * d) {
        int f = k / d, u = k - f * d;
        val = __float2half_rn(wl[((f*64 + g2) * d + u) * d + v]);
    }
    g_Bh[BBASE + idx] = val;
}

__device__ __forceinline__ void kZA_body(int b, int tid) {
    int g = b * 256 + tid;
    int e, Kp, ab, d;
    if      (g <   8192) { d=1;  ab=AB0h; e=g;          }
    else if (g <  32768) { d=3;  ab=AB1h; e=g -   8192; }
    else if (g <  73728) { d=5;  ab=AB2h; e=g -  32768; }
    else if (g < 131072) { d=7;  ab=AB3h; e=g -  73728; }
    else if (g < 204800) { d=9;  ab=AB4h; e=g - 131072; }
    else if (g < 294912) { d=11; ab=AB5h; e=g - 204800; }
    else if (g < 401408) { d=13; ab=AB6h; e=g - 294912; }
    else return;
    Kp = 16 * (d + 1);
    int row = e >> 4, kk = e & 15;
    g_Ah[ab + row * Kp + 16*d + kk] = __float2half_rn(0.f);
}

__device__ __forceinline__ void kXC_body(const float* __restrict__ x, int b, int tid) {
    int idx2 = b * 256 + tid;
    int r = idx2 / 240, j2 = idx2 - r * 240;
    int j = j2 * 2;
    float v0 = (j     < DIM6c) ? x[(size_t)r * DIM6c + j    ] : 0.f;
    float v1 = (j + 1 < DIM6c) ? x[(size_t)r * DIM6c + j + 1] : 0.f;
    *(__half2*)(g_xH + (size_t)r * PAD6 + j) = __floats2half2_rn(v0, v1);
}

__device__ __forceinline__ void kAux_body(const float* __restrict__ ico, int I,
                                          int b, int tid) {
    int idx = b * 256 + tid;
    if (idx < 64 * PAD6) {
        int n = idx / PAD6, j = idx - n * PAD6;
        g_icoH[idx] = (n < I && j < DIM6c) ?
            __float2half_rn(ico[(size_t)n * DIM6c + j]) : __float2half_rn(0.f);
    } else {
        int k = idx - 64 * PAD6;
        if (k < TROWS * 25) {
            int r = k / 25, j = DIM6c + (k - r * 25);
            g_TJh[(size_t)r * PAD6 + j] = __float2half_rn(0.f);
        }
    }
}

#define NB_H   32
#define NB_CVT 2048
#define NB_WT  2016
#define NB_ZA  1568
#define NB_XC  15360
#define NB_AUX 3320
#define O_CVT  (NB_H)
#define O_WT   (O_CVT + NB_CVT)
#define O_ZA   (O_WT + NB_WT)
#define O_XC   (O_ZA + NB_ZA)
#define O_AUX  (O_XC + NB_XC)
#define NB_ALL (O_AUX + NB_AUX)

__global__ __launch_bounds__(256) void kPrep(
    const float* traj, const float* w1s, const float* w1v,
    const float* Dout, const float* x, const float* ico, int I,
    const float* w0, const float* w1, const float* w2p, const float* w3,
    const float* w4, const float* w5, const float* w6) {
    __shared__ unsigned short t[32][33];
    const int b = blockIdx.x, tid = threadIdx.x;
    if (b < NB_H) {
        kH_body(traj, w1s, w1v, b, tid);
    } else if (b < O_WT) {
        kCvtT_body(Dout, t, b - O_CVT, tid);
    } else if (b < O_ZA) {
        int lb = b - O_WT;
        if      (lb < 8)    kWt_body<0,BB0h>(w0,  lb,        tid);
        else if (lb < 56)   kWt_body<1,BB1h>(w1,  lb - 8,    tid);
        else if (lb < 176)  kWt_body<2,BB2h>(w2p, lb - 56,   tid);
        else if (lb < 400)  kWt_body<3,BB3h>(w3,  lb - 176,  tid);
        else if (lb < 760)  kWt_body<4,BB4h>(w4,  lb - 400,  tid);
        else if (lb < 1288) kWt_body<5,BB5h>(w5,  lb - 760,  tid);
        else                kWt_body<6,BB6h>(w6,  lb - 1288, tid);
    } else if (b < O_XC) {
        kZA_body(b - O_ZA, tid);
    } else if (b < O_AUX) {
        kXC_body(x, b - O_XC, tid);
    } else {
        kAux_body(ico, I, b - O_AUX, tid);
    }
}

// ============ kSig ============
__global__ __launch_bounds__(256) void kSig(const float* __restrict__ Din) {
    __shared__ float Hs[32][10];
    const int m0 = blockIdx.y * 32;
    const int k0 = blockIdx.x * 512 + threadIdx.x * 2;
    for (int i = threadIdx.x; i < 320; i += 256)
        Hs[i/10][i%10] = g_H[m0*10 + i];
    __syncthreads();
    float dr0[10], dr1[10];
    #pragma unroll
    for (int q = 0; q < 10; q++) { dr0[q] = Din[k0*10 + q]; dr1[q] = Din[k0*10 + 10 + q]; }
    #pragma unroll 4
    for (int m = 0; m < 32; m++) {
        float a0 = 0.f, a1 = 0.f;
        #pragma unroll
        for (int q = 0; q < 10; q++) { a0 += Hs[m][q] * dr0[q]; a1 += Hs[m][q] * dr1[q]; }
        __half2 h = __floats2half2_rn(fmaxf(a0, 0.f), fmaxf(a1, 0.f));
        *(__half2*)(g_sigH + (size_t)(m0 + m) * Gc + k0) = h;
    }
}

// ===== scatter into per-l fp16 A ([btm][fu], padded Kp) =====
__device__ __forceinline__ void scatterA(int row, int col, float val) {
    if (col >= DIM6c) return;
    __half tv = __float2half_rn(val);
    int bt = row >> 4, f = row & 15;
    if (col < 1) {
        g_Ah[AB0h + bt * 32 + f] = tv;
    } else if (col < 10) {
        int r = col - 1, u = r / 3, m = r - u*3;
        g_Ah[AB1h + (bt*3 + m) * 64 + f*3 + u] = tv;
    } else if (col < 35) {
        int r = col - 10, u = r / 5, m = r - u*5;
        g_Ah[AB2h + (bt*5 + m) * 96 + f*5 + u] = tv;
    } else if (col < 84) {
        int r = col - 35, u = r / 7, m = r - u*7;
        g_Ah[AB3h + (bt*7 + m) * 128 + f*7 + u] = tv;
    } else if (col < 165) {
        int r = col - 84, u = r / 9, m = r - u*9;
        g_Ah[AB4h + (bt*9 + m) * 160 + f*9 + u] = tv;
    } else if (col < 286) {
        int r = col - 165, u = r / 11, m = r - u*11;
        g_Ah[AB5h + (bt*11 + m) * 192 + f*11 + u] = tv;
    } else {
        int r = col - 286, u = r / 13, m = r - u*13;
        g_Ah[AB6h + (bt*13 + m) * 224 + f*13 + u] = tv;
    }
}

// ============ kBh: fp16 mma GEMM with ldmatrix. CTA 128x128, BK=64 ====
#define STAGE_B 18432
__global__ __launch_bounds__(256) void kBh() {
    extern __shared__ __align__(16) char smb[];
    const int n0 = blockIdx.x * 128;
    const int m0 = blockIdx.y * 128;
    const int tid = threadIdx.x;
    const int wid = tid >> 5, lane = tid & 31;
    const int wm = wid >> 1, wn = wid & 1;
    const int lr = lane >> 2;
    const int lc = lane & 3;

    float acc[2][8][4];
    #pragma unroll
    for (int mi = 0; mi < 2; mi++)
        #pragma unroll
        for (int nj = 0; nj < 8; nj++)
            #pragma unroll
            for (int r = 0; r < 4; r++) acc[mi][nj][r] = 0.f;

    auto issue = [&](int buf, int k0) {
        #pragma unroll
        for (int i = 0; i < 4; i++) {
            int id = tid + i*256;
            int row = id >> 3, cc = id & 7;
            CP_ASYNC16(smem_u32(smb + buf*STAGE_B + row*144 + cc*16),
                       g_sigH + (size_t)(m0 + row) * Gc + k0 + cc*8);
            CP_ASYNC16(smem_u32(smb + 2*STAGE_B + buf*STAGE_B + row*144 + cc*16),
                       g_BnH + (size_t)(n0 + row) * Gc + k0 + cc*8);
        }
    };

    issue(0, 0);  CP_COMMIT();
    issue(1, 64); CP_COMMIT();

    const int a_row_in = (lane & 15);
    const int a_koff   = (lane >> 4) << 4;
    const int b_row_in = ((lane >> 4) << 3) + (lane & 7);
    const int b_koff   = ((lane >> 3) & 1) << 4;

    const int NIT = Gc / 64;
    for (int it = 0; it < NIT; it++) {
        const int buf = it & 1;
        const unsigned int Abase = smem_u32(smb + buf*STAGE_B);
        const unsigned int Bbase = smem_u32(smb + 2*STAGE_B + buf*STAGE_B);
        CP_WAIT1();
        __syncthreads();

        #pragma unroll
        for (int kc = 0; kc < 4; kc++) {
            unsigned int afr[2][4];
            #pragma unroll
            for (int mi = 0; mi < 2; mi++) {
                int row = wm*32 + mi*16 + a_row_in;
                LDSM4(afr[mi][0], afr[mi][1], afr[mi][2], afr[mi][3],
                      Abase + row*144 + kc*32 + a_koff);
            }
            unsigned int bfr[8][2];
            #pragma unroll
            for (int njp = 0; njp < 4; njp++) {
                int row = wn*64 + njp*16 + b_row_in;
                LDSM4(bfr[2*njp][0], bfr[2*njp][1], bfr[2*njp+1][0], bfr[2*njp+1][1],
                      Bbase + row*144 + kc*32 + b_koff);
            }
            #pragma unroll
            for (int nj = 0; nj < 8; nj++)
                #pragma unroll
                for (int mi = 0; mi < 2; mi++)
                    MMA_F16(acc[mi][nj][0], acc[mi][nj][1], acc[mi][nj][2], acc[mi][nj][3],
                            afr[mi][0], afr[mi][1], afr[mi][2], afr[mi][3],
                            bfr[nj][0], bfr[nj][1]);
        }
        __syncthreads();
        int nk = (it + 2) * 64;
        if (nk < Gc) issue(buf, nk);
        CP_COMMIT();
    }

    #pragma unroll
    for (int mi = 0; mi < 2; mi++) {
        #pragma unroll
        for (int nj = 0; nj < 8; nj++) {
            int row = m0 + wm*32 + mi*16 + lr;
            int col = n0 + wn*64 + nj*8 + lc*2;
            scatterA(row,     col,     acc[mi][nj][0] * DUNSCALE);
            scatterA(row,     col + 1, acc[mi][nj][1] * DUNSCALE);
            scatterA(row + 8, col,     acc[mi][nj][2] * DUNSCALE);
            scatterA(row + 8, col + 1, acc[mi][nj][3] * DUNSCALE);
        }
    }
}

// ============ kCgemm v4: full-K-resident fp16, 16B fills, one sync =========
// SH = Kp+8 halves -> row byte stride 32d+48 (16B aligned); SW = 8d+12
#define SMEMC 89088
template<int L, int OFF, int ABASE, int BBASE>
__device__ __forceinline__ void kCh_body(char* sm) {
    constexpr int d    = 2*L + 1;
    constexpr int Kp   = 16 * (d + 1);
    constexpr int SH   = Kp + 8;
    constexpr int SW   = SH / 2;
    constexpr int Mdim = 512 * d;
    constexpr int TM   = Mdim / 128;
    constexpr int TN   = d;
    const int tile = blockIdx.x;
    if (tile >= TM * TN) return;
    const int m0 = (tile % TM) * 128;
    const int n0 = (tile / TM) * 64;
    const int tid = threadIdx.x;
    const int wid = tid >> 5, lane = tid & 31;
    const int wm = wid >> 1, wn = wid & 1;
    const int lr = lane >> 2, lc = lane & 3;

    __half* Ash = (__half*)sm;
    __half* Bsh = Ash + 128 * SH;

    constexpr int C8 = Kp / 8;            // 16B chunks per row
    for (int c = tid; c < 128 * C8; c += 256) {
        int row = c / C8, ch = c - row * C8;
        CP_ASYNC16(smem_u32(Ash + row*SH + ch*8),
                   g_Ah + ABASE + (size_t)(m0 + row) * Kp + ch*8);
    }
    for (int c = tid; c < 64 * C8; c += 256) {
        int row = c / C8, ch = c - row * C8;
        CP_ASYNC16(smem_u32(Bsh + row*SH + ch*8),
                   g_Bh + BBASE + (size_t)(n0 + row) * Kp + ch*8);
    }
    CP_COMMIT();
    CP_WAIT0();
    __syncthreads();

    const unsigned int* A32 = (const unsigned int*)Ash;
    const unsigned int* B32 = (const unsigned int*)Bsh;

    float acc[2][4][4];
    #pragma unroll
    for (int mi = 0; mi < 2; mi++)
        #pragma unroll
        for (int nj = 0; nj < 4; nj++)
            #pragma unroll
            for (int r = 0; r < 4; r++) acc[mi][nj][r] = 0.f;

    #pragma unroll
    for (int kc = 0; kc < d + 1; kc++) {
        const int w0 = kc*8 + lc;
        unsigned int afr[2][4];
        #pragma unroll
        for (int mi = 0; mi < 2; mi++) {
            int rb = wm*32 + mi*16 + lr;
            afr[mi][0] = A32[(rb    )*SW + w0    ];
            afr[mi][1] = A32[(rb + 8)*SW + w0    ];
            afr[mi][2] = A32[(rb    )*SW + w0 + 4];
            afr[mi][3] = A32[(rb + 8)*SW + w0 + 4];
        }
        #pragma unroll
        for (int nj = 0; nj < 4; nj++) {
            int nb = wn*32 + nj*8 + lr;
            unsigned int b0 = B32[nb*SW + w0    ];
            unsigned int b1 = B32[nb*SW + w0 + 4];
            #pragma unroll
            for (int mi = 0; mi < 2; mi++)
                MMA_F16(acc[mi][nj][0], acc[mi][nj][1], acc[mi][nj][2], acc[mi][nj][3],
                        afr[mi][0], afr[mi][1], afr[mi][2], afr[mi][3], b0, b1);
        }
    }

    const float scale = 0.25f * rsqrtf((float)d);
    #pragma unroll
    for (int mi = 0; mi < 2; mi++) {
        #pragma unroll
        for (int nj = 0; nj < 4; nj++) {
            #pragma unroll
            for (int rr = 0; rr < 2; rr++) {
                int row = m0 + wm*32 + mi*16 + lr + rr*8;
                int bt = row / d, mm = row - bt * d;
                #pragma unroll
                for (int cc = 0; cc < 2; cc++) {
                    int col = n0 + wn*32 + nj*8 + lc*2 + cc;
                    int g2 = col / d, v = col - g2 * d;
                    g_TJh[(size_t)(bt*64 + g2) * PAD6 + OFF + v*d + mm] =
                        __float2half_rn(acc[mi][nj][rr*2 + cc] * scale);
                }
            }
        }
    }
}
__global__ __launch_bounds__(256) void kCgemm() {
    extern __shared__ __align__(16) char smc[];
    switch (blockIdx.y) {
        case 0: kCh_body<0,0,  AB0h,BB0h>(smc); break;
        case 1: kCh_body<1,1,  AB1h,BB1h>(smc); break;
        case 2: kCh_body<2,10, AB2h,BB2h>(smc); break;
        case 3: kCh_body<3,35, AB3h,BB3h>(smc); break;
        case 4: kCh_body<4,84, AB4h,BB4h>(smc); break;
        case 5: kCh_body<5,165,AB5h,BB5h>(smc); break;
        case 6: kCh_body<6,286,AB6h,BB6h>(smc); break;
    }
}

// ============ kDmma: fp16 mma, 2-stage cp.async pipeline ====================
__global__ __launch_bounds__(256) void kDmma(float* __restrict__ out, int I) {
    __shared__ __align__(16) __half As[2][128][36];
    __shared__ __align__(16) __half Bs[2][64][36];
    const int r0 = blockIdx.x * 128;
    const __half* Ap = (r0 < XROWS) ? (g_xH + (size_t)r0 * PAD6)
                                    : (g_TJh + (size_t)(r0 - XROWS) * PAD6);
    const int tid = threadIdx.x;
    const int wid = tid >> 5, lane = tid & 31;
    const int wm = wid >> 1, wn = wid & 1;
    const int lr = lane >> 2;
    const int lc = lane & 3;

    float acc[2][4][4];
    #pragma unroll
    for (int mi = 0; mi < 2; mi++)
        #pragma unroll
        for (int nj = 0; nj < 4; nj++)
            #pragma unroll
            for (int r = 0; r < 4; r++) acc[mi][nj][r] = 0.f;

    auto issue = [&](int buf, int j0) {
        #pragma unroll
        for (int i = 0; i < 4; i++) {
            int id = tid + i*256;
            int r = id >> 3, ch = id & 7;
            CP_ASYNC8(smem_u32((char*)&As[buf][0][0] + r*72 + ch*8),
                      Ap + (size_t)r * PAD6 + j0 + ch*4);
        }
        #pragma unroll
        for (int i = 0; i < 2; i++) {
            int id = tid + i*256;
            int n = id >> 3, ch = id & 7;
            CP_ASYNC8(smem_u32((char*)&Bs[buf][0][0] + n*72 + ch*8),
                      g_icoH + (size_t)n * PAD6 + j0 + ch*4);
        }
    };

    issue(0, 0);  CP_COMMIT();
    issue(1, 32); CP_COMMIT();

    const int NIT = PAD6 / 32;   // 15
    for (int it = 0; it < NIT; it++) {
        const int buf = it & 1;
        const unsigned int* A32 = (const unsigned int*)&As[buf][0][0];
        const unsigned int* B32 = (const unsigned int*)&Bs[buf][0][0];
        CP_WAIT1();
        __syncthreads();

        #pragma unroll
        for (int kc = 0; kc < 2; kc++) {
            const int w0 = kc*8 + lc;
            unsigned int afr[2][4];
            #pragma unroll
            for (int mi = 0; mi < 2; mi++) {
                int rb = wm*32 + mi*16 + lr;
                afr[mi][0] = A32[(rb    )*18 + w0    ];
                afr[mi][1] = A32[(rb + 8)*18 + w0    ];
                afr[mi][2] = A32[(rb    )*18 + w0 + 4];
                afr[mi][3] = A32[(rb + 8)*18 + w0 + 4];
            }
            #pragma unroll
            for (int nj = 0; nj < 4; nj++) {
                int nb = wn*32 + nj*8 + lr;
                unsigned int b0 = B32[nb*18 + w0    ];
                unsigned int b1 = B32[nb*18 + w0 + 4];
                #pragma unroll
                for (int mi = 0; mi < 2; mi++)
                    MMA_F16(acc[mi][nj][0], acc[mi][nj][1], acc[mi][nj][2], acc[mi][nj][3],
                            afr[mi][0], afr[mi][1], afr[mi][2], afr[mi][3], b0, b1);
            }
        }
        __syncthreads();
        int nj0 = (it + 2) * 32;
        if (nj0 < PAD6) issue(buf, nj0);
        CP_COMMIT();
    }

    #pragma unroll
    for (int mi = 0; mi < 2; mi++) {
        #pragma unroll
        for (int nj = 0; nj < 4; nj++) {
            int row = r0 + wm*32 + mi*16 + lr;
            int col = wn*32 + nj*8 + lc*2;
            if (col < I) {
                out[(size_t)row * I + col] = acc[mi][nj][0];
                out[(size_t)(row + 8) * I + col] = acc[mi][nj][2];
                if (col + 1 < I) {
                    out[(size_t)row * I + col + 1] = acc[mi][nj][1];
                    out[(size_t)(row + 8) * I + col + 1] = acc[mi][nj][3];
                }
            }
        }
    }
}

extern "C" void kernel_launch(void* const* d_in, const int* in_sizes, int n_in,
                              void* d_out, int out_size) {
    const float *x = nullptr, *traj = nullptr, *w1s = nullptr, *w1v = nullptr;
    const float *Din = nullptr, *Dout = nullptr, *ico = nullptr;
    const float* w2[7] = {};
    int icoN = 60;

    for (int i = 0; i < n_in; i++) {
        int sz = in_sizes[i];
        const float* p = (const float*)d_in[i];
        switch (sz) {
            case 7454720: x    = p; break;
            case 5120:    traj = p; break;
            case 16:      w1s  = p; break;
            case 144:     w1v  = p; break;
            case 40960:   Din  = p; break;
            case 1863680: Dout = p; break;
            case 1024:    w2[0] = p; break;
            case 9216:    w2[1] = p; break;
            case 25600:   w2[2] = p; break;
            case 50176:   w2[3] = p; break;
            case 82944:   w2[4] = p; break;
            case 123904:  w2[5] = p; break;
            case 173056:  w2[6] = p; break;
            default:      ico = p; icoN = sz / DIM6c; break;
        }
    }
    float* out = (float*)d_out;

    const int SMEMB = 4 * STAGE_B;
    cudaFuncSetAttribute(kBh, cudaFuncAttributeMaxDynamicSharedMemorySize, SMEMB);
    cudaFuncSetAttribute(kCgemm, cudaFuncAttributeMaxDynamicSharedMemorySize, SMEMC);

    kPrep<<<NB_ALL, 256>>>(traj, w1s, w1v, Dout, x, ico, icoN,
                           w2[0], w2[1], w2[2], w2[3], w2[4], w2[5], w2[6]);
    kSig<<<dim3(Gc/512, MROWS/32), 256>>>(Din);

    kBh<<<dim3(4, MROWS/128), 256, SMEMB>>>();

    kCgemm<<<dim3(676, 7), 256, SMEMC>>>();

    kDmma<<<(XROWS + TROWS)/128, 256>>>(out, icoN);
}